// round 14
// baseline (speedup 1.0000x reference)
#include <cuda_runtime.h>
#include <cuda_fp16.h>
#include <cstdint>

// PS-ROI Align, single fused kernel. 4-lane groups: each tap is one
// ld.shared.v4.b32 (16B/lane = full 64B fp16 pixel per group), halving LDS
// instruction count and per-roi addressing vs the 8-lane version. Tables
// store pre-replicated half2 weights + packed indices (uint4/record).
// Grid 49 x 15 = 735 blocks = one full wave at occ 5.

namespace {
constexpr int POOLN       = 7;
constexpr int TOTAL_BINS  = 49;
constexpr int ALPHA       = 32;
constexpr int HH          = 20;
constexpr int WW          = 20;
constexpr int THREADS     = 256;
constexpr int GROUPS      = THREADS / 4;        // 64 rois per iter
constexpr int CHUNKS      = 15;                 // 49*15 = 735 blocks = 1 wave @ occ5
constexpr int SMEM_F4     = HH * WW * (ALPHA / 4);  // 3200 8B fp16 chunks
constexpr int SLICE_BYTES = SMEM_F4 * 8;            // 25600
constexpr int TBL_PAD     = 548;                    // per_chunk(547)+1
constexpr int TX_OFF      = SLICE_BYTES;            // 25600
constexpr int TY_OFF      = TX_OFF + TBL_PAD * 16;  // 34368
constexpr int SMEM_BYTES  = TY_OFF + TBL_PAD * 16;  // 43136
}

// fp32 axis record (intermediate): .x = bitcast i0|i1<<8|i2<<16 ; .y/.z/.w =
// W0,W1,W2 pre-scaled by 0.5 (two axes' product = the 0.25 mean factor).
__device__ __forceinline__ float4 axis_record(float origin, float step, int pos)
{
    const float sc = 19.0f / 20.0f;
    float c1 = (origin + (float)pos * step) * sc;
    float c2 = (origin + (float)(pos + 1) * step) * sc;

    float f1 = floorf(c1), f2 = floorf(c2);
    float w1 = c1 - f1,    w2 = c2 - f2;
    float v1 = (c1 >= 0.0f && c1 <= 19.0f) ? 1.0f : 0.0f;
    float v2 = (c2 >= 0.0f && c2 <= 19.0f) ? 1.0f : 0.0f;

    int a1 = min(max((int)f1, 0), 19);
    int b1 = min(a1 + 1, 19);
    int a2 = min(max((int)f2, 0), 19);
    int b2 = min(a2 + 1, 19);

    int o1 = b1 - a1;
    int o2 = min(max(a2 - a1, 0), 2);
    int o3 = min(max(b2 - a1, 0), 2);

    float u1 = v1 - v1 * w1;
    float u2 = v1 * w1;
    float u3 = v2 - v2 * w2;
    float u4 = v2 * w2;

    float W0 = u1 + (o1 == 0 ? u2 : 0.0f) + (o2 == 0 ? u3 : 0.0f) + (o3 == 0 ? u4 : 0.0f);
    float W1 =      (o1 == 1 ? u2 : 0.0f) + (o2 == 1 ? u3 : 0.0f) + (o3 == 1 ? u4 : 0.0f);
    float W2 =                              (o2 == 2 ? u3 : 0.0f) + (o3 == 2 ? u4 : 0.0f);

    int i0 = a1;
    int i1 = min(a1 + 1, 19);
    int i2 = min(a1 + 2, 19);

    float4 rec;
    rec.x = __int_as_float(i0 | (i1 << 8) | (i2 << 16));
    rec.y = 0.5f * W0; rec.z = 0.5f * W1; rec.w = 0.5f * W2;
    return rec;
}

// ---- helpers ----
__device__ __forceinline__ uint32_t h2u(__half2 h) {
    return *reinterpret_cast<uint32_t*>(&h);
}
__device__ __forceinline__ __half2 u2h(uint32_t u) {
    return *reinterpret_cast<__half2*>(&u);
}
__device__ __forceinline__ uint4 lds_u4(uint32_t addr) {
    uint4 v;
    asm("ld.shared.v4.b32 {%0, %1, %2, %3}, [%4];"
        : "=r"(v.x), "=r"(v.y), "=r"(v.z), "=r"(v.w) : "r"(addr));
    return v;
}
__device__ __forceinline__ void sts_u4(uint32_t addr, uint4 v) {
    asm volatile("st.shared.v4.b32 [%0], {%1, %2, %3, %4};"
                 :: "r"(addr), "r"(v.x), "r"(v.y), "r"(v.z), "r"(v.w));
}

__global__ __launch_bounds__(THREADS, 5)
void psroi_fused_kernel(const float4* __restrict__ img4,
                        const float4* __restrict__ rois4,
                        float4* __restrict__ out4,
                        int R)
{
    extern __shared__ uint32_t sh[];

    const int bin = blockIdx.x;        // 0..48
    const int bx  = bin / POOLN;
    const int by  = bin % POOLN;

    const uint32_t smem0 = (uint32_t)__cvta_generic_to_shared(sh);
    const uint32_t txb   = smem0 + TX_OFF;
    const uint32_t tyb   = smem0 + TY_OFF;

    const int per_chunk = (R + CHUNKS - 1) / CHUNKS;     // 547
    const int roi_begin = blockIdx.y * per_chunk;
    const int roi_end   = min(roi_begin + per_chunk, R);
    const int cnt       = roi_end - roi_begin;

    // ---- phase A: axis records (pre-replicated half2 weights + packed idx) ----
    for (int i = threadIdx.x; i < cnt; i += THREADS) {
        float4 r = __ldg(&rois4[roi_begin + i]);     // x, y, w, h
        float4 ax = axis_record(r.x, r.z * (1.0f / 7.0f), bx);
        float4 ay = axis_record(r.y, r.w * (1.0f / 7.0f), by);
        uint4 rx, ry;
        rx.x = h2u(__float2half2_rn(ax.y));
        rx.y = h2u(__float2half2_rn(ax.z));
        rx.z = h2u(__float2half2_rn(ax.w));
        rx.w = (uint32_t)__float_as_int(ax.x);
        ry.x = h2u(__float2half2_rn(ay.y));
        ry.y = h2u(__float2half2_rn(ay.z));
        ry.z = h2u(__float2half2_rn(ay.w));
        ry.w = (uint32_t)__float_as_int(ay.x);
        sts_u4(txb + (uint32_t)i * 16u, rx);
        sts_u4(tyb + (uint32_t)i * 16u, ry);
    }

    // ---- phase B: stage the bin's feature slice as fp16 (25.6KB) ----
    {
        const int binoff4 = bin * (ALPHA / 4);
        #pragma unroll 4
        for (int p = threadIdx.x; p < SMEM_F4; p += THREADS) {
            int pix = p >> 3;
            int aq  = p & 7;
            float4 v = img4[pix * (TOTAL_BINS * ALPHA / 4) + binoff4 + aq];
            __half2 h0 = __float22half2_rn(make_float2(v.x, v.y));
            __half2 h1 = __float22half2_rn(make_float2(v.z, v.w));
            asm volatile("st.shared.v2.b32 [%0], {%1, %2};"
                         :: "r"(smem0 + (uint32_t)p * 8u), "r"(h2u(h0)), "r"(h2u(h1)));
        }
    }
    __syncthreads();

    // ---- phase C: main loop. 4-lane groups, 16B (8 alphas) per lane. ----
    const int grp = threadIdx.x >> 2;   // 0..63
    const int q   = threadIdx.x & 3;    // 16B quarter of the 64B pixel
    const int iters = (cnt + GROUPS - 1) / GROUPS;

    const uint32_t sbase = smem0 + (uint32_t)(q * 16);

    // prefetch first iteration's records (SMEM loads, 4-lane broadcast)
    int i_n = grp;
    int ic  = min(i_n, cnt - 1);
    uint4 wxn = lds_u4(txb + (uint32_t)ic * 16u);
    uint4 wyn = lds_u4(tyb + (uint32_t)ic * 16u);

    #pragma unroll 1
    for (int it = 0; it < iters; ++it) {
        const int i = i_n;
        const uint4 wx = wxn;
        const uint4 wy = wyn;

        i_n += GROUPS;
        ic = min(i_n, cnt - 1);
        wxn = lds_u4(txb + (uint32_t)ic * 16u);
        wyn = lds_u4(tyb + (uint32_t)ic * 16u);

        const uint32_t px = wx.w;
        const uint32_t py = wy.w;
        // column byte offsets: x*64 ; row byte offsets: y*20*64 = y*1280
        const uint32_t c0 = sbase + ((px & 255u) << 6);
        const uint32_t c1 = sbase + (((px >> 8) & 255u) << 6);
        const uint32_t c2 = sbase + (((px >> 16) & 255u) << 6);
        const uint32_t r0 = (py & 255u) * 1280u;
        const uint32_t r1 = ((py >> 8) & 255u) * 1280u;
        const uint32_t r2 = ((py >> 16) & 255u) * 1280u;

        const __half2 wx0h = u2h(wx.x), wx1h = u2h(wx.y), wx2h = u2h(wx.z);
        const __half2 wy0h = u2h(wy.x), wy1h = u2h(wy.y), wy2h = u2h(wy.z);

        __half2 acc0, acc1, acc2, acc3;

        // row macro: u_k = wx0*t0_k + wx1*t1_k + wx2*t2_k ; acc += wy_r * u
        #define ROW(RADDR, WYH, FIRST) do {                          \
            uint4 t0_ = lds_u4((RADDR) + c0);                        \
            uint4 t1_ = lds_u4((RADDR) + c1);                        \
            uint4 t2_ = lds_u4((RADDR) + c2);                        \
            __half2 u0_ = __hmul2(wx0h, u2h(t0_.x));                 \
            __half2 u1_ = __hmul2(wx0h, u2h(t0_.y));                 \
            __half2 u2_ = __hmul2(wx0h, u2h(t0_.z));                 \
            __half2 u3_ = __hmul2(wx0h, u2h(t0_.w));                 \
            u0_ = __hfma2(wx1h, u2h(t1_.x), u0_);                    \
            u1_ = __hfma2(wx1h, u2h(t1_.y), u1_);                    \
            u2_ = __hfma2(wx1h, u2h(t1_.z), u2_);                    \
            u3_ = __hfma2(wx1h, u2h(t1_.w), u3_);                    \
            u0_ = __hfma2(wx2h, u2h(t2_.x), u0_);                    \
            u1_ = __hfma2(wx2h, u2h(t2_.y), u1_);                    \
            u2_ = __hfma2(wx2h, u2h(t2_.z), u2_);                    \
            u3_ = __hfma2(wx2h, u2h(t2_.w), u3_);                    \
            if (FIRST) {                                             \
                acc0 = __hmul2((WYH), u0_);                          \
                acc1 = __hmul2((WYH), u1_);                          \
                acc2 = __hmul2((WYH), u2_);                          \
                acc3 = __hmul2((WYH), u3_);                          \
            } else {                                                 \
                acc0 = __hfma2((WYH), u0_, acc0);                    \
                acc1 = __hfma2((WYH), u1_, acc1);                    \
                acc2 = __hfma2((WYH), u2_, acc2);                    \
                acc3 = __hfma2((WYH), u3_, acc3);                    \
            }                                                        \
        } while (0)

        ROW(r0, wy0h, true);
        ROW(r1, wy1h, false);
        ROW(r2, wy2h, false);
        #undef ROW

        if (i < cnt) {
            const int roi = roi_begin + i;
            float2 f0 = __half22float2(acc0);
            float2 f1 = __half22float2(acc1);
            float2 f2 = __half22float2(acc2);
            float2 f3 = __half22float2(acc3);
            // lane writes 32B: out float4 index = roi*392 + bin*8 + q*2
            const int ob = roi * (TOTAL_BINS * ALPHA / 4) + bin * (ALPHA / 4) + q * 2;
            out4[ob]     = make_float4(f0.x, f0.y, f1.x, f1.y);
            out4[ob + 1] = make_float4(f2.x, f2.y, f3.x, f3.y);
        }
    }
}

extern "C" void kernel_launch(void* const* d_in, const int* in_sizes, int n_in,
                              void* d_out, int out_size)
{
    const float* p0 = (const float*)d_in[0];
    const float* p1 = (const float*)d_in[1];
    const float* img  = p0;
    const float* rois = p1;
    int rois_elems = in_sizes[1];
    if (in_sizes[0] < in_sizes[1]) {
        img = p1; rois = p0; rois_elems = in_sizes[0];
    }
    const int R = rois_elems / 4;      // 8192

    cudaFuncSetAttribute(psroi_fused_kernel,
                         cudaFuncAttributeMaxDynamicSharedMemorySize, SMEM_BYTES);
    dim3 grid(TOTAL_BINS, CHUNKS);     // 49 x 15 = 735 blocks: 1 wave @ occ 5
    psroi_fused_kernel<<<grid, THREADS, SMEM_BYTES>>>(
        (const float4*)img, (const float4*)rois, (float4*)d_out, R);
}

// round 15
// speedup vs baseline: 1.0681x; 1.0681x over previous
#include <cuda_runtime.h>
#include <cuda_fp16.h>
#include <cstdint>

// PS-ROI Align, single fused kernel. R13's 8-lane inner loop (best measured)
// + R14's pre-converted half2 weight tables (no per-iter cvt) + true
// single-wave grid at occ 5 (49 x 15 = 735 blocks <= 740 resident).

namespace {
constexpr int POOLN       = 7;
constexpr int TOTAL_BINS  = 49;
constexpr int ALPHA       = 32;
constexpr int HH          = 20;
constexpr int WW          = 20;
constexpr int THREADS     = 256;
constexpr int GROUPS      = THREADS / 8;        // 32 rois per iter
constexpr int CHUNKS      = 15;                 // 735 blocks = 1 wave @ occ5
constexpr int SMEM_F4     = HH * WW * (ALPHA / 4);  // 3200 8B fp16 chunks
constexpr int SLICE_BYTES = SMEM_F4 * 8;            // 25600
constexpr int TBL_PAD     = 548;                    // per_chunk(547)+1
constexpr int TX_OFF      = SLICE_BYTES;            // 25600
constexpr int TY_OFF      = TX_OFF + TBL_PAD * 16;  // 34368
constexpr int SMEM_BYTES  = TY_OFF + TBL_PAD * 16;  // 43136
}

// fp32 axis record (intermediate): .x = bitcast i0|i1<<8|i2<<16 ; .y/.z/.w =
// W0,W1,W2 pre-scaled by 0.5 (two axes' product = the 0.25 mean factor).
__device__ __forceinline__ float4 axis_record(float origin, float step, int pos)
{
    const float sc = 19.0f / 20.0f;
    float c1 = (origin + (float)pos * step) * sc;
    float c2 = (origin + (float)(pos + 1) * step) * sc;

    float f1 = floorf(c1), f2 = floorf(c2);
    float w1 = c1 - f1,    w2 = c2 - f2;
    float v1 = (c1 >= 0.0f && c1 <= 19.0f) ? 1.0f : 0.0f;
    float v2 = (c2 >= 0.0f && c2 <= 19.0f) ? 1.0f : 0.0f;

    int a1 = min(max((int)f1, 0), 19);
    int b1 = min(a1 + 1, 19);
    int a2 = min(max((int)f2, 0), 19);
    int b2 = min(a2 + 1, 19);

    int o1 = b1 - a1;
    int o2 = min(max(a2 - a1, 0), 2);
    int o3 = min(max(b2 - a1, 0), 2);

    float u1 = v1 - v1 * w1;
    float u2 = v1 * w1;
    float u3 = v2 - v2 * w2;
    float u4 = v2 * w2;

    float W0 = u1 + (o1 == 0 ? u2 : 0.0f) + (o2 == 0 ? u3 : 0.0f) + (o3 == 0 ? u4 : 0.0f);
    float W1 =      (o1 == 1 ? u2 : 0.0f) + (o2 == 1 ? u3 : 0.0f) + (o3 == 1 ? u4 : 0.0f);
    float W2 =                              (o2 == 2 ? u3 : 0.0f) + (o3 == 2 ? u4 : 0.0f);

    int i0 = a1;
    int i1 = min(a1 + 1, 19);
    int i2 = min(a1 + 2, 19);

    float4 rec;
    rec.x = __int_as_float(i0 | (i1 << 8) | (i2 << 16));
    rec.y = 0.5f * W0; rec.z = 0.5f * W1; rec.w = 0.5f * W2;
    return rec;
}

// ---- helpers ----
__device__ __forceinline__ uint32_t h2u(__half2 h) {
    return *reinterpret_cast<uint32_t*>(&h);
}
__device__ __forceinline__ __half2 u2h(uint32_t u) {
    return *reinterpret_cast<__half2*>(&u);
}
__device__ __forceinline__ void lds_h2x2(__half2& h0, __half2& h1,
                                         uint32_t addr) {
    uint32_t lo, hi;
    asm("ld.shared.v2.b32 {%0, %1}, [%2];" : "=r"(lo), "=r"(hi) : "r"(addr));
    h0 = u2h(lo);
    h1 = u2h(hi);
}
__device__ __forceinline__ uint4 lds_u4(uint32_t addr) {
    uint4 v;
    asm("ld.shared.v4.b32 {%0, %1, %2, %3}, [%4];"
        : "=r"(v.x), "=r"(v.y), "=r"(v.z), "=r"(v.w) : "r"(addr));
    return v;
}
__device__ __forceinline__ void sts_u4(uint32_t addr, uint4 v) {
    asm volatile("st.shared.v4.b32 [%0], {%1, %2, %3, %4};"
                 :: "r"(addr), "r"(v.x), "r"(v.y), "r"(v.z), "r"(v.w));
}

__global__ __launch_bounds__(THREADS, 5)
void psroi_fused_kernel(const float4* __restrict__ img4,
                        const float4* __restrict__ rois4,
                        float4* __restrict__ out4,
                        int R)
{
    extern __shared__ uint32_t sh[];

    const int bin = blockIdx.x;        // 0..48
    const int bx  = bin / POOLN;
    const int by  = bin % POOLN;

    const uint32_t smem0 = (uint32_t)__cvta_generic_to_shared(sh);
    const uint32_t txb   = smem0 + TX_OFF;
    const uint32_t tyb   = smem0 + TY_OFF;

    const int per_chunk = (R + CHUNKS - 1) / CHUNKS;     // 547
    const int roi_begin = blockIdx.y * per_chunk;
    const int roi_end   = min(roi_begin + per_chunk, R);
    const int cnt       = roi_end - roi_begin;

    // ---- phase A: axis records, pre-converted to half2 + packed indices ----
    for (int i = threadIdx.x; i < cnt; i += THREADS) {
        float4 r = __ldg(&rois4[roi_begin + i]);     // x, y, w, h
        float4 ax = axis_record(r.x, r.z * (1.0f / 7.0f), bx);
        float4 ay = axis_record(r.y, r.w * (1.0f / 7.0f), by);
        uint4 rx, ry;
        rx.x = h2u(__float2half2_rn(ax.y));
        rx.y = h2u(__float2half2_rn(ax.z));
        rx.z = h2u(__float2half2_rn(ax.w));
        rx.w = (uint32_t)__float_as_int(ax.x);
        ry.x = h2u(__float2half2_rn(ay.y));
        ry.y = h2u(__float2half2_rn(ay.z));
        ry.z = h2u(__float2half2_rn(ay.w));
        ry.w = (uint32_t)__float_as_int(ay.x);
        sts_u4(txb + (uint32_t)i * 16u, rx);
        sts_u4(tyb + (uint32_t)i * 16u, ry);
    }

    // ---- phase B: stage the bin's feature slice as fp16 (25.6KB) ----
    {
        const int binoff4 = bin * (ALPHA / 4);
        #pragma unroll 4
        for (int p = threadIdx.x; p < SMEM_F4; p += THREADS) {
            int pix = p >> 3;
            int aq  = p & 7;
            float4 v = img4[pix * (TOTAL_BINS * ALPHA / 4) + binoff4 + aq];
            __half2 h0 = __float22half2_rn(make_float2(v.x, v.y));
            __half2 h1 = __float22half2_rn(make_float2(v.z, v.w));
            asm volatile("st.shared.v2.b32 [%0], {%1, %2};"
                         :: "r"(smem0 + (uint32_t)p * 8u), "r"(h2u(h0)), "r"(h2u(h1)));
        }
    }
    __syncthreads();

    // ---- phase C: main loop (8-lane groups, 8B per lane) ----
    const int grp = threadIdx.x >> 3;
    const int q   = threadIdx.x & 7;
    const int iters = (cnt + GROUPS - 1) / GROUPS;

    const uint32_t sbase = smem0 + (uint32_t)(q * 8);

    // prefetch first iteration's records (SMEM broadcast loads)
    int i_n = grp;
    int ic  = min(i_n, cnt - 1);
    uint4 wxn = lds_u4(txb + (uint32_t)ic * 16u);
    uint4 wyn = lds_u4(tyb + (uint32_t)ic * 16u);

    #pragma unroll 1
    for (int it = 0; it < iters; ++it) {
        const int i = i_n;
        const uint4 wx = wxn;
        const uint4 wy = wyn;

        i_n += GROUPS;
        ic = min(i_n, cnt - 1);
        wxn = lds_u4(txb + (uint32_t)ic * 16u);
        wyn = lds_u4(tyb + (uint32_t)ic * 16u);

        const uint32_t px = wx.w;
        const uint32_t py = wy.w;
        // column byte offsets: x*64 ; row byte offsets: y*20*64 = y*1280
        const uint32_t c0 = sbase + ((px & 255u) << 6);
        const uint32_t c1 = sbase + (((px >> 8) & 255u) << 6);
        const uint32_t c2 = sbase + (((px >> 16) & 255u) << 6);
        const uint32_t r0 = (py & 255u) * 1280u;
        const uint32_t r1 = ((py >> 8) & 255u) * 1280u;
        const uint32_t r2 = ((py >> 16) & 255u) * 1280u;

        const __half2 wx0h = u2h(wx.x), wx1h = u2h(wx.y), wx2h = u2h(wx.z);
        const __half2 wy0h = u2h(wy.x), wy1h = u2h(wy.y), wy2h = u2h(wy.z);

        #define ROWSUM_H(UA, UB, RADDR) do {             \
            __half2 v0a_, v0b_, v1a_, v1b_, v2a_, v2b_;  \
            lds_h2x2(v0a_, v0b_, (RADDR) + c0);          \
            lds_h2x2(v1a_, v1b_, (RADDR) + c1);          \
            lds_h2x2(v2a_, v2b_, (RADDR) + c2);          \
            UA = __hmul2(wx0h, v0a_);                    \
            UB = __hmul2(wx0h, v0b_);                    \
            UA = __hfma2(wx1h, v1a_, UA);                \
            UB = __hfma2(wx1h, v1b_, UB);                \
            UA = __hfma2(wx2h, v2a_, UA);                \
            UB = __hfma2(wx2h, v2b_, UB);                \
        } while (0)

        __half2 u0a, u0b, u1a, u1b, u2a, u2b;
        ROWSUM_H(u0a, u0b, r0);
        ROWSUM_H(u1a, u1b, r1);
        ROWSUM_H(u2a, u2b, r2);
        #undef ROWSUM_H

        // y-combine in fp16; only two final conversions to fp32.
        __half2 b0 = __hmul2(wy0h, u0a);
        __half2 b1 = __hmul2(wy0h, u0b);
        b0 = __hfma2(wy1h, u1a, b0);
        b1 = __hfma2(wy1h, u1b, b1);
        b0 = __hfma2(wy2h, u2a, b0);
        b1 = __hfma2(wy2h, u2b, b1);

        if (i < cnt) {
            const int roi = roi_begin + i;
            float2 f0 = __half22float2(b0);
            float2 f1 = __half22float2(b1);
            float4 o = make_float4(f0.x, f0.y, f1.x, f1.y);
            out4[roi * (TOTAL_BINS * ALPHA / 4) + bin * (ALPHA / 4) + q] = o;
        }
    }
}

extern "C" void kernel_launch(void* const* d_in, const int* in_sizes, int n_in,
                              void* d_out, int out_size)
{
    const float* p0 = (const float*)d_in[0];
    const float* p1 = (const float*)d_in[1];
    const float* img  = p0;
    const float* rois = p1;
    int rois_elems = in_sizes[1];
    if (in_sizes[0] < in_sizes[1]) {
        img = p1; rois = p0; rois_elems = in_sizes[0];
    }
    const int R = rois_elems / 4;      // 8192

    cudaFuncSetAttribute(psroi_fused_kernel,
                         cudaFuncAttributeMaxDynamicSharedMemorySize, SMEM_BYTES);
    dim3 grid(TOTAL_BINS, CHUNKS);     // 49 x 15 = 735 blocks: 1 wave @ occ 5
    psroi_fused_kernel<<<grid, THREADS, SMEM_BYTES>>>(
        (const float4*)img, (const float4*)rois, (float4*)d_out, R);
}